// round 4
// baseline (speedup 1.0000x reference)
#include <cuda_runtime.h>
#include <cuda_bf16.h>
#include <cstdint>

// Problem constants
#define T_SEQ   2048
#define N_BATCH 4
#define C_DIM   768
#define N_HEADS 12
#define H_DIM   64
#define M_ROWS  (N_BATCH * T_SEQ)   // 8192

// Scratch (static __device__ arrays: allocation-free per harness rules)
__device__ float g_qkv[(size_t)M_ROWS * 3 * C_DIM];   // [8192, 2304]
__device__ float g_att[(size_t)M_ROWS * C_DIM];       // [8192, 768]

// ===========================================================================
// mma.sync helpers (sm_80-class ISA, valid at plain sm_100 PTX target)
// ===========================================================================
__device__ __forceinline__ uint32_t smem_u32(const void* p) {
    uint32_t a;
    asm("{ .reg .u64 t; cvta.to.shared.u64 t, %1; cvt.u32.u64 %0, t; }"
        : "=r"(a) : "l"(p));
    return a;
}

#define LDSM4(r, addr) \
    asm volatile("ldmatrix.sync.aligned.m8n8.x4.shared.b16 {%0,%1,%2,%3}, [%4];" \
                 : "=r"((r)[0]), "=r"((r)[1]), "=r"((r)[2]), "=r"((r)[3]) \
                 : "r"(addr))

#define MMA_BF16(c, a, b) \
    asm volatile("mma.sync.aligned.m16n8k16.row.col.f32.bf16.bf16.f32 " \
                 "{%0,%1,%2,%3}, {%4,%5,%6,%7}, {%8,%9}, {%0,%1,%2,%3};" \
                 : "+f"((c)[0]), "+f"((c)[1]), "+f"((c)[2]), "+f"((c)[3]) \
                 : "r"((a)[0]), "r"((a)[1]), "r"((a)[2]), "r"((a)[3]), \
                   "r"((b)[0]), "r"((b)[1]))

// Split two floats into packed bf16 hi/lo pairs (x in low half)
__device__ __forceinline__ void split2(float x, float y, uint32_t& hi, uint32_t& lo) {
    __nv_bfloat16 hx = __float2bfloat16_rn(x);
    __nv_bfloat16 hy = __float2bfloat16_rn(y);
    float lx = x - __bfloat162float(hx);
    float ly = y - __bfloat162float(hy);
    __nv_bfloat16 lxh = __float2bfloat16_rn(lx);
    __nv_bfloat16 lyh = __float2bfloat16_rn(ly);
    hi = (uint32_t)__bfloat16_as_ushort(hx) | ((uint32_t)__bfloat16_as_ushort(hy) << 16);
    lo = (uint32_t)__bfloat16_as_ushort(lxh) | ((uint32_t)__bfloat16_as_ushort(lyh) << 16);
}

// Fast 2^t on the FMA pipe (t <= 0 in softmax use). rel err ~3e-6.
__device__ __forceinline__ float exp2_fast(float t) {
    t = fmaxf(t, -100.0f);
    float n = rintf(t);
    float f = t - n;                        // [-0.5, 0.5]
    float u = f * 0.6931471805599453f;      // f*ln2, |u| <= 0.347
    float r = 8.3333333e-3f;                // 1/120
    r = fmaf(r, u, 4.1666667e-2f);          // 1/24
    r = fmaf(r, u, 1.6666667e-1f);          // 1/6
    r = fmaf(r, u, 5.0e-1f);
    r = fmaf(r, u, 1.0f);
    r = fmaf(r, u, 1.0f);
    int e = (int)n;                         // exact (n integer-valued, >= -100)
    return r * __int_as_float((e + 127) << 23);
}

// ===========================================================================
// bf16x3-split tensor-core GEMM:  C[M,N] = A[M,K] @ W[N,K]^T + bias[N]
// Block 128x128, BK=32, 8 warps (warp tile 64x32), fp32 accum in registers.
// Two smem stages (dynamic smem), one __syncthreads per chunk:
// STS of chunk c+1 overlaps LDSM/MMA of chunk c.
// ===========================================================================
#define SROW 40                 // halves per smem row (32 data + 8 pad)
#define ARR_U32 (128 * SROW / 2)      // 2560 u32 per array
#define STG_U32 (4 * ARR_U32)         // Ahi,Alo,Bhi,Blo per stage
#define STG_BYTES (STG_U32 * 4)       // 40960
#define GEMM_DSMEM (2 * STG_BYTES)    // 81920

__device__ __forceinline__ void store_chunk(uint32_t* stg, int sIdx,
                                            const float4* pa, const float4* pb) {
    #pragma unroll
    for (int i = 0; i < 4; i++) {
        uint32_t h0, l0, h1, l1;
        split2(pa[i].x, pa[i].y, h0, l0);
        split2(pa[i].z, pa[i].w, h1, l1);
        stg[0*ARR_U32 + sIdx + i*4]     = h0;
        stg[0*ARR_U32 + sIdx + i*4 + 1] = h1;
        stg[1*ARR_U32 + sIdx + i*4]     = l0;
        stg[1*ARR_U32 + sIdx + i*4 + 1] = l1;
        split2(pb[i].x, pb[i].y, h0, l0);
        split2(pb[i].z, pb[i].w, h1, l1);
        stg[2*ARR_U32 + sIdx + i*4]     = h0;
        stg[2*ARR_U32 + sIdx + i*4 + 1] = h1;
        stg[3*ARR_U32 + sIdx + i*4]     = l0;
        stg[3*ARR_U32 + sIdx + i*4 + 1] = l1;
    }
}

__global__ __launch_bounds__(256, 1)
void gemm_bf16x3(const float* __restrict__ A,
                 const float* __restrict__ W,
                 const float* __restrict__ bias,
                 float* __restrict__ C,
                 int Nd, int Kd)
{
    extern __shared__ __align__(16) uint32_t dsm[];

    const int tid  = threadIdx.x;
    const int lane = tid & 31;
    const int wid  = tid >> 5;
    const int wm   = wid & 1;    // warp row (2)
    const int wn   = wid >> 1;   // warp col (4)
    const int bn = blockIdx.x, bm = blockIdx.y;

    // -------- producer mapping: thread -> (row, 4-col base) --------
    const int lr = tid >> 1;
    const int cb = (tid & 1) * 4;
    const float* ga = A + (size_t)(bm * 128 + lr) * Kd + cb;
    const float* gb = W + (size_t)(bn * 128 + lr) * Kd + cb;
    const int sIdx = lr * (SROW / 2) + (cb >> 1);   // u32 index within array

    float4 pa[4], pb[4];
    #pragma unroll
    for (int i = 0; i < 4; i++) {
        pa[i] = *(const float4*)(ga + i * 8);
        pb[i] = *(const float4*)(gb + i * 8);
    }

    float acc[4][4][4];
    #pragma unroll
    for (int mt = 0; mt < 4; mt++)
        #pragma unroll
        for (int nt = 0; nt < 4; nt++)
            #pragma unroll
            for (int q = 0; q < 4; q++) acc[mt][nt][q] = 0.0f;

    // -------- ldmatrix lane base addresses (stage 0; add s*STG_BYTES) ------
    const uint32_t sb = smem_u32(dsm);
    const uint32_t aOff = ((uint32_t)(wm * 64 + (lane & 15)) * SROW + (lane >> 4) * 8) * 2;
    const uint32_t bOff = ((uint32_t)(wn * 32 + ((lane >> 4) & 1) * 8 + (lane & 7)) * SROW
                          + ((lane >> 3) & 1) * 8) * 2;
    const uint32_t aHiB = sb + aOff;
    const uint32_t aLoB = sb + 1*ARR_U32*4 + aOff;
    const uint32_t bHiB = sb + 2*ARR_U32*4 + bOff;
    const uint32_t bLoB = sb + 3*ARR_U32*4 + bOff;

    const int nch = Kd / 32;

    // prologue: stage 0 filled with chunk 0
    store_chunk(dsm, sIdx, pa, pb);
    __syncthreads();

    for (int c = 0; c < nch; c++) {
        const int s = c & 1;
        const uint32_t so = (uint32_t)s * STG_BYTES;

        if (c + 1 < nch) {   // global prefetch of next chunk
            #pragma unroll
            for (int i = 0; i < 4; i++) {
                pa[i] = *(const float4*)(ga + (size_t)(c + 1) * 32 + i * 8);
                pb[i] = *(const float4*)(gb + (size_t)(c + 1) * 32 + i * 8);
            }
        }

        #pragma unroll
        for (int ks = 0; ks < 2; ks++) {
            uint32_t ah[4][4], al[4][4], bh[4][2], bl[4][2];
            #pragma unroll
            for (int mt = 0; mt < 4; mt++) {
                const uint32_t ad = (uint32_t)(mt * 16 * SROW + ks * 16) * 2 + so;
                LDSM4(ah[mt], aHiB + ad);
                LDSM4(al[mt], aLoB + ad);
            }
            #pragma unroll
            for (int p = 0; p < 2; p++) {
                const uint32_t bd = (uint32_t)(p * 16 * SROW + ks * 16) * 2 + so;
                uint32_t r[4];
                LDSM4(r, bHiB + bd);
                bh[2*p][0] = r[0]; bh[2*p][1] = r[1];
                bh[2*p+1][0] = r[2]; bh[2*p+1][1] = r[3];
                LDSM4(r, bLoB + bd);
                bl[2*p][0] = r[0]; bl[2*p][1] = r[1];
                bl[2*p+1][0] = r[2]; bl[2*p+1][1] = r[3];
            }
            #pragma unroll
            for (int mt = 0; mt < 4; mt++)
                #pragma unroll
                for (int nt = 0; nt < 4; nt++) {
                    MMA_BF16(acc[mt][nt], ah[mt], bh[nt]);
                    MMA_BF16(acc[mt][nt], al[mt], bh[nt]);
                    MMA_BF16(acc[mt][nt], ah[mt], bl[nt]);
                }
        }

        if (c + 1 < nch)     // fill the other stage while MMAs drain
            store_chunk(dsm + ((c + 1) & 1) * STG_U32, sIdx, pa, pb);
        __syncthreads();
    }

    // -------- epilogue: acc + bias -> C --------
    const int gid = lane >> 2, tig = lane & 3;
    const int row0 = bm * 128 + wm * 64;
    const int col0 = bn * 128 + wn * 32;
    #pragma unroll
    for (int mt = 0; mt < 4; mt++)
        #pragma unroll
        for (int nt = 0; nt < 4; nt++) {
            const int r  = row0 + mt * 16 + gid;
            const int cc = col0 + nt * 8 + tig * 2;
            const float2 bz = *(const float2*)(bias + cc);
            float2 o0, o1;
            o0.x = acc[mt][nt][0] + bz.x; o0.y = acc[mt][nt][1] + bz.y;
            o1.x = acc[mt][nt][2] + bz.x; o1.y = acc[mt][nt][3] + bz.y;
            *(float2*)(C + (size_t)r * Nd + cc)       = o0;
            *(float2*)(C + (size_t)(r + 8) * Nd + cc) = o1;
        }
}

// ===========================================================================
// Flash attention, fp32 SIMT. Softmax in log2-space: Q pre-scaled by
// 8*log2(e); exp via FMA-pipe exp2_fast (kills the MUFU bottleneck).
// ===========================================================================
#define QT_LD 132
#define KT_LD 68
#define QSCALE 11.541560327111707f   // 8 * log2(e)

__global__ __launch_bounds__(256)
void attn_flash(const float* __restrict__ qkv, float* __restrict__ attout)
{
    extern __shared__ float sm[];
    float* Qt  = sm;
    float* Kt  = Qt  + 64*QT_LD;
    float* Vs  = Kt  + 64*KT_LD;
    float* Pt  = Vs  + 64*KT_LD;
    float* red = Pt  + 64*QT_LD;
    float* m_s = red + 128*17;
    float* l_s = m_s + 128;
    float* scl = l_s + 128;

    const int tid = threadIdx.x;
    const int tx  = tid & 15;
    const int ty  = tid >> 4;
    const int m0  = blockIdx.x * 128;
    const int h   = blockIdx.y;
    const int b   = blockIdx.z;

    const float* qb = qkv + (size_t)b * T_SEQ * (3*C_DIM) + h * H_DIM;
    const float* kb = qb + C_DIM;
    const float* vb = qb + 2*C_DIM;

    for (int idx = tid; idx < 128*64; idx += 256) {
        int d = idx & 63, r = idx >> 6;
        Qt[d*QT_LD + r] = qb[(size_t)(m0 + r)*(3*C_DIM) + d] * QSCALE;
    }
    if (tid < 128) { m_s[tid] = -1e30f; l_s[tid] = 0.0f; }

    float o[8][4];
    #pragma unroll
    for (int i = 0; i < 8; i++)
        #pragma unroll
        for (int j = 0; j < 4; j++) o[i][j] = 0.0f;
    __syncthreads();

    for (int kt = 0; kt < T_SEQ/64; kt++) {
        const int n0 = kt * 64;
        for (int idx = tid; idx < 64*64; idx += 256) {
            int d = idx & 63, r = idx >> 6;
            Kt[d*KT_LD + r] = kb[(size_t)(n0 + r)*(3*C_DIM) + d];
        }
        for (int idx = tid; idx < 64*64; idx += 256) {
            int d = idx & 63, r = idx >> 6;
            Vs[r*KT_LD + d] = vb[(size_t)(n0 + r)*(3*C_DIM) + d];
        }
        __syncthreads();

        float s[8][4];
        #pragma unroll
        for (int i = 0; i < 8; i++)
            #pragma unroll
            for (int j = 0; j < 4; j++) s[i][j] = 0.0f;
        #pragma unroll 8
        for (int d = 0; d < 64; d++) {
            float qr[8], kr[4];
            *(float4*)&qr[0] = *(const float4*)&Qt[d*QT_LD + ty*8];
            *(float4*)&qr[4] = *(const float4*)&Qt[d*QT_LD + ty*8 + 4];
            *(float4*)&kr[0] = *(const float4*)&Kt[d*KT_LD + tx*4];
            #pragma unroll
            for (int i = 0; i < 8; i++)
                #pragma unroll
                for (int j = 0; j < 4; j++)
                    s[i][j] = fmaf(qr[i], kr[j], s[i][j]);
        }

        #pragma unroll
        for (int i = 0; i < 8; i++) {
            float rm = fmaxf(fmaxf(s[i][0], s[i][1]), fmaxf(s[i][2], s[i][3]));
            red[(ty*8 + i)*17 + tx] = rm;
        }
        __syncthreads();
        if (tid < 128) {
            float mo = m_s[tid];
            float mx = red[tid*17];
            #pragma unroll
            for (int t2 = 1; t2 < 16; t2++) mx = fmaxf(mx, red[tid*17 + t2]);
            float mn = fmaxf(mo, mx);
            m_s[tid] = mn;
            scl[tid] = exp2_fast(mo - mn);
        }
        __syncthreads();

        #pragma unroll
        for (int i = 0; i < 8; i++) {
            const int row = ty*8 + i;
            const float mn = m_s[row];
            const float sc = scl[row];
            float rs = 0.0f;
            #pragma unroll
            for (int j = 0; j < 4; j++) {
                float p = exp2_fast(s[i][j] - mn);
                rs += p;
                Pt[(tx*4 + j)*QT_LD + row] = p;
            }
            red[row*17 + tx] = rs;
            #pragma unroll
            for (int j = 0; j < 4; j++) o[i][j] *= sc;
        }
        __syncthreads();
        if (tid < 128) {
            float rs = 0.0f;
            #pragma unroll
            for (int t2 = 0; t2 < 16; t2++) rs += red[tid*17 + t2];
            l_s[tid] = l_s[tid]*scl[tid] + rs;
        }

        #pragma unroll 8
        for (int n = 0; n < 64; n++) {
            float pr[8], vr[4];
            *(float4*)&pr[0] = *(const float4*)&Pt[n*QT_LD + ty*8];
            *(float4*)&pr[4] = *(const float4*)&Pt[n*QT_LD + ty*8 + 4];
            *(float4*)&vr[0] = *(const float4*)&Vs[n*KT_LD + tx*4];
            #pragma unroll
            for (int i = 0; i < 8; i++)
                #pragma unroll
                for (int j = 0; j < 4; j++)
                    o[i][j] = fmaf(pr[i], vr[j], o[i][j]);
        }
        __syncthreads();
    }

    #pragma unroll
    for (int i = 0; i < 8; i++) {
        const int row = ty*8 + i;
        const float inv = 1.0f / l_s[row];
        float4 v;
        v.x = o[i][0]*inv; v.y = o[i][1]*inv; v.z = o[i][2]*inv; v.w = o[i][3]*inv;
        *(float4*)(attout + (size_t)(b*T_SEQ + m0 + row)*C_DIM + h*H_DIM + tx*4) = v;
    }
}

// ===========================================================================
extern "C" void kernel_launch(void* const* d_in, const int* in_sizes, int n_in,
                              void* d_out, int out_size)
{
    (void)in_sizes; (void)n_in; (void)out_size;
    const float* x      = (const float*)d_in[0];
    const float* qkv_w  = (const float*)d_in[1];
    const float* qkv_b  = (const float*)d_in[2];
    const float* proj_w = (const float*)d_in[3];
    const float* proj_b = (const float*)d_in[4];
    float* out = (float*)d_out;

    float *qkv_ptr, *att_ptr;
    cudaGetSymbolAddress((void**)&qkv_ptr, g_qkv);
    cudaGetSymbolAddress((void**)&att_ptr, g_att);

    constexpr size_t ATTN_SMEM =
        (size_t)(64*QT_LD + 64*KT_LD + 64*KT_LD + 64*QT_LD + 128*17 + 3*128) * sizeof(float);
    cudaFuncSetAttribute(attn_flash, cudaFuncAttributeMaxDynamicSharedMemorySize, (int)ATTN_SMEM);
    cudaFuncSetAttribute(gemm_bf16x3, cudaFuncAttributeMaxDynamicSharedMemorySize, GEMM_DSMEM);

    // 1) QKV GEMM: [8192,768] x [2304,768]^T + b -> g_qkv   (bf16x3 tensor)
    gemm_bf16x3<<<dim3(3*C_DIM/128, M_ROWS/128), 256, GEMM_DSMEM>>>(
        x, qkv_w, qkv_b, qkv_ptr, 3*C_DIM, C_DIM);
    // 2) flash attention -> g_att
    attn_flash<<<dim3(T_SEQ/128, N_HEADS, N_BATCH), 256, ATTN_SMEM>>>(qkv_ptr, att_ptr);
    // 3) proj GEMM: [8192,768] x [768,768]^T + b -> out     (bf16x3 tensor)
    gemm_bf16x3<<<dim3(C_DIM/128, M_ROWS/128), 256, GEMM_DSMEM>>>(
        att_ptr, proj_w, proj_b, out, C_DIM, C_DIM);
}

// round 5
// speedup vs baseline: 1.5378x; 1.5378x over previous
#include <cuda_runtime.h>
#include <cuda_bf16.h>
#include <cstdint>

// Problem constants
#define T_SEQ   2048
#define N_BATCH 4
#define C_DIM   768
#define N_HEADS 12
#define H_DIM   64
#define M_ROWS  (N_BATCH * T_SEQ)   // 8192

// Scratch (static __device__ arrays: allocation-free per harness rules)
__device__ float g_qkv[(size_t)M_ROWS * 3 * C_DIM];   // [8192, 2304]
__device__ float g_att[(size_t)M_ROWS * C_DIM];       // [8192, 768]

// ===========================================================================
// mma.sync helpers (sm_80-class ISA, valid at plain sm_100 PTX target)
// ===========================================================================
__device__ __forceinline__ uint32_t smem_u32(const void* p) {
    uint32_t a;
    asm("{ .reg .u64 t; cvta.to.shared.u64 t, %1; cvt.u32.u64 %0, t; }"
        : "=r"(a) : "l"(p));
    return a;
}

#define LDSM4(r, addr) \
    asm volatile("ldmatrix.sync.aligned.m8n8.x4.shared.b16 {%0,%1,%2,%3}, [%4];" \
                 : "=r"((r)[0]), "=r"((r)[1]), "=r"((r)[2]), "=r"((r)[3]) \
                 : "r"(addr))

#define LDSM4T(r, addr) \
    asm volatile("ldmatrix.sync.aligned.m8n8.x4.trans.shared.b16 {%0,%1,%2,%3}, [%4];" \
                 : "=r"((r)[0]), "=r"((r)[1]), "=r"((r)[2]), "=r"((r)[3]) \
                 : "r"(addr))

#define MMA_BF16(c, a, b) \
    asm volatile("mma.sync.aligned.m16n8k16.row.col.f32.bf16.bf16.f32 " \
                 "{%0,%1,%2,%3}, {%4,%5,%6,%7}, {%8,%9}, {%0,%1,%2,%3};" \
                 : "+f"((c)[0]), "+f"((c)[1]), "+f"((c)[2]), "+f"((c)[3]) \
                 : "r"((a)[0]), "r"((a)[1]), "r"((a)[2]), "r"((a)[3]), \
                   "r"((b)[0]), "r"((b)[1]))

// Split two floats into packed bf16 hi/lo pairs (x in low half)
__device__ __forceinline__ void split2(float x, float y, uint32_t& hi, uint32_t& lo) {
    __nv_bfloat16 hx = __float2bfloat16_rn(x);
    __nv_bfloat16 hy = __float2bfloat16_rn(y);
    float lx = x - __bfloat162float(hx);
    float ly = y - __bfloat162float(hy);
    __nv_bfloat16 lxh = __float2bfloat16_rn(lx);
    __nv_bfloat16 lyh = __float2bfloat16_rn(ly);
    hi = (uint32_t)__bfloat16_as_ushort(hx) | ((uint32_t)__bfloat16_as_ushort(hy) << 16);
    lo = (uint32_t)__bfloat16_as_ushort(lxh) | ((uint32_t)__bfloat16_as_ushort(lyh) << 16);
}

// Fast 2^t on the FMA pipe (t <= 0 in softmax use). rel err ~3e-6.
__device__ __forceinline__ float exp2_fast(float t) {
    t = fmaxf(t, -100.0f);
    float n = rintf(t);
    float f = t - n;                        // [-0.5, 0.5]
    float u = f * 0.6931471805599453f;      // f*ln2
    float r = 8.3333333e-3f;
    r = fmaf(r, u, 4.1666667e-2f);
    r = fmaf(r, u, 1.6666667e-1f);
    r = fmaf(r, u, 5.0e-1f);
    r = fmaf(r, u, 1.0f);
    r = fmaf(r, u, 1.0f);
    int e = (int)n;
    return r * __int_as_float((e + 127) << 23);
}

// ===========================================================================
// bf16x3-split tensor-core GEMM (round-3 version, 375us):
// C[M,N] = A[M,K] @ W[N,K]^T + bias[N]. Block 128x128, BK=32, 8 warps.
// ===========================================================================
#define SROW 40   // halves per smem row (32 data + 8 pad)

__global__ __launch_bounds__(256, 1)
void gemm_bf16x3(const float* __restrict__ A,
                 const float* __restrict__ W,
                 const float* __restrict__ bias,
                 float* __restrict__ C,
                 int Nd, int Kd)
{
    __shared__ __align__(16) uint32_t sAhi[128 * SROW / 2];
    __shared__ __align__(16) uint32_t sAlo[128 * SROW / 2];
    __shared__ __align__(16) uint32_t sBhi[128 * SROW / 2];
    __shared__ __align__(16) uint32_t sBlo[128 * SROW / 2];

    const int tid  = threadIdx.x;
    const int lane = tid & 31;
    const int wid  = tid >> 5;
    const int wm   = wid & 1;
    const int wn   = wid >> 1;
    const int bn = blockIdx.x, bm = blockIdx.y;

    const int lr = tid >> 1;
    const int cb = (tid & 1) * 4;
    const float* ga = A + (size_t)(bm * 128 + lr) * Kd + cb;
    const float* gb = W + (size_t)(bn * 128 + lr) * Kd + cb;
    const int sIdx = lr * (SROW / 2) + (cb >> 1);

    float4 pa[4], pb[4];
    #pragma unroll
    for (int i = 0; i < 4; i++) {
        pa[i] = *(const float4*)(ga + i * 8);
        pb[i] = *(const float4*)(gb + i * 8);
    }

    float acc[4][4][4];
    #pragma unroll
    for (int mt = 0; mt < 4; mt++)
        #pragma unroll
        for (int nt = 0; nt < 4; nt++)
            #pragma unroll
            for (int q = 0; q < 4; q++) acc[mt][nt][q] = 0.0f;

    const uint32_t aOff = ((uint32_t)(wm * 64 + (lane & 15)) * SROW + (lane >> 4) * 8) * 2;
    const uint32_t bOff = ((uint32_t)(wn * 32 + ((lane >> 4) & 1) * 8 + (lane & 7)) * SROW
                          + ((lane >> 3) & 1) * 8) * 2;
    const uint32_t aHiB = smem_u32(sAhi) + aOff, aLoB = smem_u32(sAlo) + aOff;
    const uint32_t bHiB = smem_u32(sBhi) + bOff, bLoB = smem_u32(sBlo) + bOff;

    const int nch = Kd / 32;
    for (int c = 0; c < nch; c++) {
        #pragma unroll
        for (int i = 0; i < 4; i++) {
            uint32_t h0, l0, h1, l1;
            split2(pa[i].x, pa[i].y, h0, l0);
            split2(pa[i].z, pa[i].w, h1, l1);
            sAhi[sIdx + i * 4] = h0; sAhi[sIdx + i * 4 + 1] = h1;
            sAlo[sIdx + i * 4] = l0; sAlo[sIdx + i * 4 + 1] = l1;
            split2(pb[i].x, pb[i].y, h0, l0);
            split2(pb[i].z, pb[i].w, h1, l1);
            sBhi[sIdx + i * 4] = h0; sBhi[sIdx + i * 4 + 1] = h1;
            sBlo[sIdx + i * 4] = l0; sBlo[sIdx + i * 4 + 1] = l1;
        }
        __syncthreads();

        if (c + 1 < nch) {
            #pragma unroll
            for (int i = 0; i < 4; i++) {
                pa[i] = *(const float4*)(ga + (size_t)(c + 1) * 32 + i * 8);
                pb[i] = *(const float4*)(gb + (size_t)(c + 1) * 32 + i * 8);
            }
        }

        #pragma unroll
        for (int ks = 0; ks < 2; ks++) {
            uint32_t ah[4][4], al[4][4], bh[4][2], bl[4][2];
            #pragma unroll
            for (int mt = 0; mt < 4; mt++) {
                const uint32_t ad = (uint32_t)(mt * 16 * SROW + ks * 16) * 2;
                LDSM4(ah[mt], aHiB + ad);
                LDSM4(al[mt], aLoB + ad);
            }
            #pragma unroll
            for (int p = 0; p < 2; p++) {
                const uint32_t bd = (uint32_t)(p * 16 * SROW + ks * 16) * 2;
                uint32_t r[4];
                LDSM4(r, bHiB + bd);
                bh[2*p][0] = r[0]; bh[2*p][1] = r[1];
                bh[2*p+1][0] = r[2]; bh[2*p+1][1] = r[3];
                LDSM4(r, bLoB + bd);
                bl[2*p][0] = r[0]; bl[2*p][1] = r[1];
                bl[2*p+1][0] = r[2]; bl[2*p+1][1] = r[3];
            }
            #pragma unroll
            for (int mt = 0; mt < 4; mt++)
                #pragma unroll
                for (int nt = 0; nt < 4; nt++) {
                    MMA_BF16(acc[mt][nt], ah[mt], bh[nt]);
                    MMA_BF16(acc[mt][nt], al[mt], bh[nt]);
                    MMA_BF16(acc[mt][nt], ah[mt], bl[nt]);
                }
        }
        __syncthreads();
    }

    const int gid = lane >> 2, tig = lane & 3;
    const int row0 = bm * 128 + wm * 64;
    const int col0 = bn * 128 + wn * 32;
    #pragma unroll
    for (int mt = 0; mt < 4; mt++)
        #pragma unroll
        for (int nt = 0; nt < 4; nt++) {
            const int r  = row0 + mt * 16 + gid;
            const int cc = col0 + nt * 8 + tig * 2;
            const float2 bz = *(const float2*)(bias + cc);
            float2 o0, o1;
            o0.x = acc[mt][nt][0] + bz.x; o0.y = acc[mt][nt][1] + bz.y;
            o1.x = acc[mt][nt][2] + bz.x; o1.y = acc[mt][nt][3] + bz.y;
            *(float2*)(C + (size_t)r * Nd + cc)       = o0;
            *(float2*)(C + (size_t)(r + 8) * Nd + cc) = o1;
        }
}

// ===========================================================================
// MMA flash attention (FA2-style). Block = 128 q-rows x 1 head, 8 warps x
// 16 q-rows. bf16x3 split for QK^T and PV; softmax in C-fragments with quad
// shfl reductions; P repacked reg->reg into A-fragments. log2-space softmax
// (QSCALE = 8*log2e folded into Q), exp2 on the FMA pipe.
// ===========================================================================
#define NKROW 36    // u32 per smem row (64 halves data + 8 pad)
#define QSCALE 11.541560327111707f   // 8 * log2(e)

__global__ __launch_bounds__(256, 1)
void attn_mma(const float* __restrict__ qkv, float* __restrict__ attout)
{
    // 4 buffers [64 rows][36 u32]: K-hi, K-lo, V-hi, V-lo  (Q uses 0-1/2-3 in prologue)
    __shared__ __align__(16) uint32_t sKV[4][64 * NKROW];

    const int tid  = threadIdx.x;
    const int lane = tid & 31;
    const int w    = tid >> 5;
    const int g    = lane >> 2;   // group (row within tile)
    const int tig  = lane & 3;    // thread in group
    const int m0   = blockIdx.x * 128;
    const int h    = blockIdx.y;
    const int b    = blockIdx.z;

    const float* base = qkv + (size_t)b * T_SEQ * (3*C_DIM) + h * H_DIM;

    // ---- prologue: load Q[128x64] scaled+split into smem, then A-fragments
    {
        const int r = tid >> 1;
        const int dblk = (tid & 1) * 32;
        const float* qrow = base + (size_t)(m0 + r) * (3*C_DIM) + dblk;
        uint32_t* dhi = &sKV[0][r * NKROW + dblk / 2];
        uint32_t* dlo = &sKV[2][r * NKROW + dblk / 2];
        #pragma unroll
        for (int i = 0; i < 8; i++) {
            float4 v = *(const float4*)(qrow + i * 4);
            uint32_t h0, l0, h1, l1;
            split2(v.x * QSCALE, v.y * QSCALE, h0, l0);
            split2(v.z * QSCALE, v.w * QSCALE, h1, l1);
            dhi[i*2] = h0; dhi[i*2+1] = h1;
            dlo[i*2] = l0; dlo[i*2+1] = l1;
        }
    }
    __syncthreads();

    uint32_t qh[4][4], ql[4][4];
    {
        const int t = lane >> 3, rl = lane & 7;
        #pragma unroll
        for (int ks = 0; ks < 4; ks++) {
            const uint32_t off =
                ((uint32_t)(w * 16 + (t & 1) * 8 + rl) * NKROW + ks * 8 + (t >> 1) * 4) * 4;
            LDSM4(qh[ks], smem_u32(&sKV[0][0]) + off);
            LDSM4(ql[ks], smem_u32(&sKV[2][0]) + off);
        }
    }
    __syncthreads();   // Q fragments in regs; smem free for K/V

    float o[8][4];
    #pragma unroll
    for (int nt = 0; nt < 8; nt++)
        #pragma unroll
        for (int j = 0; j < 4; j++) o[nt][j] = 0.0f;
    float mrow0 = -1e30f, mrow1 = -1e30f, lrow0 = 0.0f, lrow1 = 0.0f;

    const uint32_t sKhi = smem_u32(&sKV[0][0]);
    const uint32_t sKlo = smem_u32(&sKV[1][0]);
    const uint32_t sVhi = smem_u32(&sKV[2][0]);
    const uint32_t sVlo = smem_u32(&sKV[3][0]);
    const int t = lane >> 3, rl = lane & 7;

    for (int kt = 0; kt < T_SEQ / 64; kt++) {
        const int n0 = kt * 64;
        // ---- cooperative K/V tile load (64x64 each), split to hi/lo ----
        {
            const int r = tid >> 2;
            const int dblk = (tid & 3) * 16;
            const float* krow = base + (size_t)(n0 + r) * (3*C_DIM) + C_DIM + dblk;
            const float* vrow = krow + C_DIM;
            uint32_t* kh = &sKV[0][r * NKROW + dblk / 2];
            uint32_t* kl = &sKV[1][r * NKROW + dblk / 2];
            uint32_t* vh = &sKV[2][r * NKROW + dblk / 2];
            uint32_t* vl = &sKV[3][r * NKROW + dblk / 2];
            #pragma unroll
            for (int i = 0; i < 4; i++) {
                float4 v = *(const float4*)(krow + i * 4);
                uint32_t h0, l0, h1, l1;
                split2(v.x, v.y, h0, l0); split2(v.z, v.w, h1, l1);
                kh[i*2] = h0; kh[i*2+1] = h1; kl[i*2] = l0; kl[i*2+1] = l1;
                v = *(const float4*)(vrow + i * 4);
                split2(v.x, v.y, h0, l0); split2(v.z, v.w, h1, l1);
                vh[i*2] = h0; vh[i*2+1] = h1; vl[i*2] = l0; vl[i*2+1] = l1;
            }
        }
        __syncthreads();

        // ---- S = Q K^T (bf16x3), accumulate over 4 k-steps ----
        float s[8][4];
        #pragma unroll
        for (int nt = 0; nt < 8; nt++)
            #pragma unroll
            for (int j = 0; j < 4; j++) s[nt][j] = 0.0f;

        #pragma unroll
        for (int ks = 0; ks < 4; ks++) {
            #pragma unroll
            for (int kb = 0; kb < 4; kb++) {
                const uint32_t off =
                    ((uint32_t)(kb * 16 + (t >> 1) * 8 + rl) * NKROW + ks * 8 + (t & 1) * 4) * 4;
                uint32_t rh[4], rlo[4];
                LDSM4(rh, sKhi + off);
                LDSM4(rlo, sKlo + off);
                MMA_BF16(s[2*kb],   qh[ks], rh);
                MMA_BF16(s[2*kb],   ql[ks], rh);
                MMA_BF16(s[2*kb],   qh[ks], rlo);
                MMA_BF16(s[2*kb+1], qh[ks], rh + 2);
                MMA_BF16(s[2*kb+1], ql[ks], rh + 2);
                MMA_BF16(s[2*kb+1], qh[ks], rlo + 2);
            }
        }

        // ---- online softmax in fragment layout ----
        float rm0 = -1e30f, rm1 = -1e30f;
        #pragma unroll
        for (int nt = 0; nt < 8; nt++) {
            rm0 = fmaxf(rm0, fmaxf(s[nt][0], s[nt][1]));
            rm1 = fmaxf(rm1, fmaxf(s[nt][2], s[nt][3]));
        }
        rm0 = fmaxf(rm0, __shfl_xor_sync(0xffffffffu, rm0, 1));
        rm0 = fmaxf(rm0, __shfl_xor_sync(0xffffffffu, rm0, 2));
        rm1 = fmaxf(rm1, __shfl_xor_sync(0xffffffffu, rm1, 1));
        rm1 = fmaxf(rm1, __shfl_xor_sync(0xffffffffu, rm1, 2));
        const float mn0 = fmaxf(mrow0, rm0);
        const float mn1 = fmaxf(mrow1, rm1);
        const float sc0 = exp2_fast(mrow0 - mn0);
        const float sc1 = exp2_fast(mrow1 - mn1);
        mrow0 = mn0; mrow1 = mn1;

        float rs0 = 0.0f, rs1 = 0.0f;
        #pragma unroll
        for (int nt = 0; nt < 8; nt++) {
            s[nt][0] = exp2_fast(s[nt][0] - mn0);
            s[nt][1] = exp2_fast(s[nt][1] - mn0);
            s[nt][2] = exp2_fast(s[nt][2] - mn1);
            s[nt][3] = exp2_fast(s[nt][3] - mn1);
            rs0 += s[nt][0] + s[nt][1];
            rs1 += s[nt][2] + s[nt][3];
        }
        rs0 += __shfl_xor_sync(0xffffffffu, rs0, 1);
        rs0 += __shfl_xor_sync(0xffffffffu, rs0, 2);
        rs1 += __shfl_xor_sync(0xffffffffu, rs1, 1);
        rs1 += __shfl_xor_sync(0xffffffffu, rs1, 2);
        lrow0 = lrow0 * sc0 + rs0;
        lrow1 = lrow1 * sc1 + rs1;

        #pragma unroll
        for (int nt = 0; nt < 8; nt++) {
            o[nt][0] *= sc0; o[nt][1] *= sc0;
            o[nt][2] *= sc1; o[nt][3] *= sc1;
        }

        // ---- O += P V (bf16x3), P repacked reg->reg into A-fragments ----
        #pragma unroll
        for (int ks2 = 0; ks2 < 4; ks2++) {
            uint32_t pah[4], pal[4];
            split2(s[2*ks2][0],   s[2*ks2][1],   pah[0], pal[0]);
            split2(s[2*ks2][2],   s[2*ks2][3],   pah[1], pal[1]);
            split2(s[2*ks2+1][0], s[2*ks2+1][1], pah[2], pal[2]);
            split2(s[2*ks2+1][2], s[2*ks2+1][3], pah[3], pal[3]);
            #pragma unroll
            for (int db = 0; db < 4; db++) {
                const uint32_t off =
                    ((uint32_t)(ks2 * 16 + (t & 1) * 8 + rl) * NKROW + db * 8 + (t >> 1) * 4) * 4;
                uint32_t rvh[4], rvl[4];
                LDSM4T(rvh, sVhi + off);
                LDSM4T(rvl, sVlo + off);
                MMA_BF16(o[2*db],   pah, rvh);
                MMA_BF16(o[2*db],   pal, rvh);
                MMA_BF16(o[2*db],   pah, rvl);
                MMA_BF16(o[2*db+1], pah, rvh + 2);
                MMA_BF16(o[2*db+1], pal, rvh + 2);
                MMA_BF16(o[2*db+1], pah, rvl + 2);
            }
        }
        __syncthreads();   // all smem reads done before next tile's stores
    }

    // ---- epilogue: O / l -> g_att [b, t, h*64 + d] ----
    const float inv0 = 1.0f / lrow0;
    const float inv1 = 1.0f / lrow1;
    const int qrow = m0 + w * 16 + g;
    float* orow0 = attout + (size_t)(b * T_SEQ + qrow) * C_DIM + h * H_DIM;
    float* orow1 = orow0 + (size_t)8 * C_DIM;
    #pragma unroll
    for (int nt = 0; nt < 8; nt++) {
        float2 v0, v1;
        v0.x = o[nt][0] * inv0; v0.y = o[nt][1] * inv0;
        v1.x = o[nt][2] * inv1; v1.y = o[nt][3] * inv1;
        *(float2*)(orow0 + nt * 8 + tig * 2) = v0;
        *(float2*)(orow1 + nt * 8 + tig * 2) = v1;
    }
}

// ===========================================================================
extern "C" void kernel_launch(void* const* d_in, const int* in_sizes, int n_in,
                              void* d_out, int out_size)
{
    (void)in_sizes; (void)n_in; (void)out_size;
    const float* x      = (const float*)d_in[0];
    const float* qkv_w  = (const float*)d_in[1];
    const float* qkv_b  = (const float*)d_in[2];
    const float* proj_w = (const float*)d_in[3];
    const float* proj_b = (const float*)d_in[4];
    float* out = (float*)d_out;

    float *qkv_ptr, *att_ptr;
    cudaGetSymbolAddress((void**)&qkv_ptr, g_qkv);
    cudaGetSymbolAddress((void**)&att_ptr, g_att);

    // 1) QKV GEMM: [8192,768] x [2304,768]^T + b -> g_qkv   (bf16x3 tensor)
    gemm_bf16x3<<<dim3(3*C_DIM/128, M_ROWS/128), 256>>>(x, qkv_w, qkv_b, qkv_ptr, 3*C_DIM, C_DIM);
    // 2) MMA flash attention -> g_att
    attn_mma<<<dim3(T_SEQ/128, N_HEADS, N_BATCH), 256>>>(qkv_ptr, att_ptr);
    // 3) proj GEMM: [8192,768] x [768,768]^T + b -> out     (bf16x3 tensor)
    gemm_bf16x3<<<dim3(C_DIM/128, M_ROWS/128), 256>>>(att_ptr, proj_w, proj_b, out, C_DIM, C_DIM);
}

// round 7
// speedup vs baseline: 1.7139x; 1.1145x over previous
#include <cuda_runtime.h>
#include <cuda_bf16.h>
#include <cstdint>

// Problem constants
#define T_SEQ   2048
#define N_BATCH 4
#define C_DIM   768
#define N_HEADS 12
#define H_DIM   64
#define M_ROWS  (N_BATCH * T_SEQ)   // 8192

// Scratch (static __device__ arrays: allocation-free per harness rules)
__device__ float g_qkv[(size_t)M_ROWS * 3 * C_DIM];   // [8192, 2304]
__device__ float g_att[(size_t)M_ROWS * C_DIM];       // [8192, 768]

// ===========================================================================
// mma.sync helpers (sm_80-class ISA, valid at plain sm_100 PTX target)
// ===========================================================================
__device__ __forceinline__ uint32_t smem_u32(const void* p) {
    uint32_t a;
    asm("{ .reg .u64 t; cvta.to.shared.u64 t, %1; cvt.u32.u64 %0, t; }"
        : "=r"(a) : "l"(p));
    return a;
}

#define LDSM4(r, addr) \
    asm volatile("ldmatrix.sync.aligned.m8n8.x4.shared.b16 {%0,%1,%2,%3}, [%4];" \
                 : "=r"((r)[0]), "=r"((r)[1]), "=r"((r)[2]), "=r"((r)[3]) \
                 : "r"(addr))

#define LDSM4T(r, addr) \
    asm volatile("ldmatrix.sync.aligned.m8n8.x4.trans.shared.b16 {%0,%1,%2,%3}, [%4];" \
                 : "=r"((r)[0]), "=r"((r)[1]), "=r"((r)[2]), "=r"((r)[3]) \
                 : "r"(addr))

#define MMA_BF16(c, a, b) \
    asm volatile("mma.sync.aligned.m16n8k16.row.col.f32.bf16.bf16.f32 " \
                 "{%0,%1,%2,%3}, {%4,%5,%6,%7}, {%8,%9}, {%0,%1,%2,%3};" \
                 : "+f"((c)[0]), "+f"((c)[1]), "+f"((c)[2]), "+f"((c)[3]) \
                 : "r"((a)[0]), "r"((a)[1]), "r"((a)[2]), "r"((a)[3]), \
                   "r"((b)[0]), "r"((b)[1]))

// Split two floats into packed bf16 hi/lo pairs (x in low half)
__device__ __forceinline__ void split2(float x, float y, uint32_t& hi, uint32_t& lo) {
    __nv_bfloat16 hx = __float2bfloat16_rn(x);
    __nv_bfloat16 hy = __float2bfloat16_rn(y);
    float lx = x - __bfloat162float(hx);
    float ly = y - __bfloat162float(hy);
    __nv_bfloat16 lxh = __float2bfloat16_rn(lx);
    __nv_bfloat16 lyh = __float2bfloat16_rn(ly);
    hi = (uint32_t)__bfloat16_as_ushort(hx) | ((uint32_t)__bfloat16_as_ushort(hy) << 16);
    lo = (uint32_t)__bfloat16_as_ushort(lxh) | ((uint32_t)__bfloat16_as_ushort(lyh) << 16);
}

// Fast 2^t on the FMA pipe (t <= 0 in softmax use). rel err ~3e-6.
__device__ __forceinline__ float exp2_fast(float t) {
    t = fmaxf(t, -100.0f);
    float n = rintf(t);
    float f = t - n;
    float u = f * 0.6931471805599453f;
    float r = 8.3333333e-3f;
    r = fmaf(r, u, 4.1666667e-2f);
    r = fmaf(r, u, 1.6666667e-1f);
    r = fmaf(r, u, 5.0e-1f);
    r = fmaf(r, u, 1.0f);
    r = fmaf(r, u, 1.0f);
    int e = (int)n;
    return r * __int_as_float((e + 127) << 23);
}

// ===========================================================================
// bf16x3-split tensor-core GEMM (verified round-3 version):
// C[M,N] = A[M,K] @ W[N,K]^T + bias[N]. Block 128x128, BK=32, 8 warps.
// ===========================================================================
#define SROW 40   // halves per smem row (32 data + 8 pad)

__global__ __launch_bounds__(256, 1)
void gemm_bf16x3(const float* __restrict__ A,
                 const float* __restrict__ W,
                 const float* __restrict__ bias,
                 float* __restrict__ C,
                 int Nd, int Kd)
{
    __shared__ __align__(16) uint32_t sAhi[128 * SROW / 2];
    __shared__ __align__(16) uint32_t sAlo[128 * SROW / 2];
    __shared__ __align__(16) uint32_t sBhi[128 * SROW / 2];
    __shared__ __align__(16) uint32_t sBlo[128 * SROW / 2];

    const int tid  = threadIdx.x;
    const int lane = tid & 31;
    const int wid  = tid >> 5;
    const int wm   = wid & 1;
    const int wn   = wid >> 1;
    const int bn = blockIdx.x, bm = blockIdx.y;

    const int lr = tid >> 1;
    const int cb = (tid & 1) * 4;
    const float* ga = A + (size_t)(bm * 128 + lr) * Kd + cb;
    const float* gb = W + (size_t)(bn * 128 + lr) * Kd + cb;
    const int sIdx = lr * (SROW / 2) + (cb >> 1);

    float4 pa[4], pb[4];
    #pragma unroll
    for (int i = 0; i < 4; i++) {
        pa[i] = *(const float4*)(ga + i * 8);
        pb[i] = *(const float4*)(gb + i * 8);
    }

    float acc[4][4][4];
    #pragma unroll
    for (int mt = 0; mt < 4; mt++)
        #pragma unroll
        for (int nt = 0; nt < 4; nt++)
            #pragma unroll
            for (int q = 0; q < 4; q++) acc[mt][nt][q] = 0.0f;

    const uint32_t aOff = ((uint32_t)(wm * 64 + (lane & 15)) * SROW + (lane >> 4) * 8) * 2;
    const uint32_t bOff = ((uint32_t)(wn * 32 + ((lane >> 4) & 1) * 8 + (lane & 7)) * SROW
                          + ((lane >> 3) & 1) * 8) * 2;
    const uint32_t aHiB = smem_u32(sAhi) + aOff, aLoB = smem_u32(sAlo) + aOff;
    const uint32_t bHiB = smem_u32(sBhi) + bOff, bLoB = smem_u32(sBlo) + bOff;

    const int nch = Kd / 32;
    for (int c = 0; c < nch; c++) {
        #pragma unroll
        for (int i = 0; i < 4; i++) {
            uint32_t h0, l0, h1, l1;
            split2(pa[i].x, pa[i].y, h0, l0);
            split2(pa[i].z, pa[i].w, h1, l1);
            sAhi[sIdx + i * 4] = h0; sAhi[sIdx + i * 4 + 1] = h1;
            sAlo[sIdx + i * 4] = l0; sAlo[sIdx + i * 4 + 1] = l1;
            split2(pb[i].x, pb[i].y, h0, l0);
            split2(pb[i].z, pb[i].w, h1, l1);
            sBhi[sIdx + i * 4] = h0; sBhi[sIdx + i * 4 + 1] = h1;
            sBlo[sIdx + i * 4] = l0; sBlo[sIdx + i * 4 + 1] = l1;
        }
        __syncthreads();

        if (c + 1 < nch) {
            #pragma unroll
            for (int i = 0; i < 4; i++) {
                pa[i] = *(const float4*)(ga + (size_t)(c + 1) * 32 + i * 8);
                pb[i] = *(const float4*)(gb + (size_t)(c + 1) * 32 + i * 8);
            }
        }

        #pragma unroll
        for (int ks = 0; ks < 2; ks++) {
            uint32_t ah[4][4], al[4][4], bh[4][2], bl[4][2];
            #pragma unroll
            for (int mt = 0; mt < 4; mt++) {
                const uint32_t ad = (uint32_t)(mt * 16 * SROW + ks * 16) * 2;
                LDSM4(ah[mt], aHiB + ad);
                LDSM4(al[mt], aLoB + ad);
            }
            #pragma unroll
            for (int p = 0; p < 2; p++) {
                const uint32_t bd = (uint32_t)(p * 16 * SROW + ks * 16) * 2;
                uint32_t r[4];
                LDSM4(r, bHiB + bd);
                bh[2*p][0] = r[0]; bh[2*p][1] = r[1];
                bh[2*p+1][0] = r[2]; bh[2*p+1][1] = r[3];
                LDSM4(r, bLoB + bd);
                bl[2*p][0] = r[0]; bl[2*p][1] = r[1];
                bl[2*p+1][0] = r[2]; bl[2*p+1][1] = r[3];
            }
            #pragma unroll
            for (int mt = 0; mt < 4; mt++)
                #pragma unroll
                for (int nt = 0; nt < 4; nt++) {
                    MMA_BF16(acc[mt][nt], ah[mt], bh[nt]);
                    MMA_BF16(acc[mt][nt], al[mt], bh[nt]);
                    MMA_BF16(acc[mt][nt], ah[mt], bl[nt]);
                }
        }
        __syncthreads();
    }

    const int gid = lane >> 2, tig = lane & 3;
    const int row0 = bm * 128 + wm * 64;
    const int col0 = bn * 128 + wn * 32;
    #pragma unroll
    for (int mt = 0; mt < 4; mt++)
        #pragma unroll
        for (int nt = 0; nt < 4; nt++) {
            const int r  = row0 + mt * 16 + gid;
            const int cc = col0 + nt * 8 + tig * 2;
            const float2 bz = *(const float2*)(bias + cc);
            float2 o0, o1;
            o0.x = acc[mt][nt][0] + bz.x; o0.y = acc[mt][nt][1] + bz.y;
            o1.x = acc[mt][nt][2] + bz.x; o1.y = acc[mt][nt][3] + bz.y;
            *(float2*)(C + (size_t)r * Nd + cc)       = o0;
            *(float2*)(C + (size_t)(r + 8) * Nd + cc) = o1;
        }
}

// ===========================================================================
// MMA flash attention, double-buffered K/V (2 smem stages, 1 sync per tile).
// Block = 128 q-rows x 1 head, 8 warps x 16 q-rows. bf16x3 split everywhere;
// softmax in C-fragments (quad shfl reductions, FMA-pipe exp2); P repacked
// reg->reg. LDG of tile kt+1 issued before the MMAs of tile kt; split+STS
// into the other stage after the MMAs.
// Q prologue: hi at stage1+0, lo at stage1 + 2*ARRU (hi spans Khi+Klo of
// stage 1: 128 rows * 36 u32 < 2*ARRU; lo spans Vhi+Vlo). NO overlap.
// ===========================================================================
#define NKROW 36                          // u32 per smem row (64 halves + pad)
#define ARRU  (64 * NKROW)                // u32 per 64x64 array (2304)
#define STAGE_U32 (4 * ARRU)              // Khi,Klo,Vhi,Vlo (9216)
#define STAGE_BYTES (STAGE_U32 * 4)       // 36864
#define ATTN_DSMEM (2 * STAGE_BYTES)      // 73728
#define QSCALE 11.541560327111707f        // 8 * log2(e)

__global__ __launch_bounds__(256, 1)
void attn_mma(const float* __restrict__ qkv, float* __restrict__ attout)
{
    extern __shared__ __align__(16) uint32_t dsm[];

    const int tid  = threadIdx.x;
    const int lane = tid & 31;
    const int w    = tid >> 5;
    const int g    = lane >> 2;
    const int tig  = lane & 3;
    const int m0   = blockIdx.x * 128;
    const int h    = blockIdx.y;
    const int b    = blockIdx.z;

    const float* base = qkv + (size_t)b * T_SEQ * (3*C_DIM) + h * H_DIM;
    const uint32_t sb = smem_u32(dsm);

    // producer mapping for K/V tiles: row = tid>>2, 16-col block = (tid&3)*16
    const int pr = tid >> 2;
    const int pd = (tid & 3) * 16;
    const float* kbase = base + C_DIM + pd;        // + (n0+pr)*3C
    const float* vbase = base + 2*C_DIM + pd;
    const int pIdx = pr * NKROW + pd / 2;          // u32 index within array

    // ---- prologue: Q (scaled+split) -> stage 1. hi at +0, lo at +2*ARRU ----
    {
        const int r = tid >> 1;
        const int dblk = (tid & 1) * 32;
        const float* qrow = base + (size_t)(m0 + r) * (3*C_DIM) + dblk;
        uint32_t* dhi = dsm + STAGE_U32 + r * NKROW + dblk / 2;
        uint32_t* dlo = dhi + 2 * ARRU;     // FIX: 2 arrays apart (no overlap)
        #pragma unroll
        for (int i = 0; i < 8; i++) {
            float4 v = *(const float4*)(qrow + i * 4);
            uint32_t h0, l0, h1, l1;
            split2(v.x * QSCALE, v.y * QSCALE, h0, l0);
            split2(v.z * QSCALE, v.w * QSCALE, h1, l1);
            dhi[i*2] = h0; dhi[i*2+1] = h1;
            dlo[i*2] = l0; dlo[i*2+1] = l1;
        }
    }
    // prefetch tile 0 while Q settles
    float4 pk[4], pv[4];
    #pragma unroll
    for (int i = 0; i < 4; i++) {
        pk[i] = *(const float4*)(kbase + (size_t)pr * (3*C_DIM) + i * 4);
        pv[i] = *(const float4*)(vbase + (size_t)pr * (3*C_DIM) + i * 4);
    }
    __syncthreads();

    uint32_t qh[4][4], ql[4][4];
    const int t = lane >> 3, rl = lane & 7;
    {
        #pragma unroll
        for (int ks = 0; ks < 4; ks++) {
            const uint32_t off =
                ((uint32_t)(w * 16 + (t & 1) * 8 + rl) * NKROW + ks * 8 + (t >> 1) * 4) * 4;
            LDSM4(qh[ks], sb + STAGE_BYTES + off);
            LDSM4(ql[ks], sb + STAGE_BYTES + 2 * ARRU * 4 + off);   // FIX: match
        }
    }
    __syncthreads();   // everyone done reading Q from stage 1

    // store tile 0 -> stage 0
    {
        uint32_t* kh = dsm + pIdx;
        #pragma unroll
        for (int i = 0; i < 4; i++) {
            uint32_t h0, l0, h1, l1;
            split2(pk[i].x, pk[i].y, h0, l0); split2(pk[i].z, pk[i].w, h1, l1);
            kh[i*2] = h0; kh[i*2+1] = h1;
            kh[ARRU + i*2] = l0; kh[ARRU + i*2+1] = l1;
            split2(pv[i].x, pv[i].y, h0, l0); split2(pv[i].z, pv[i].w, h1, l1);
            kh[2*ARRU + i*2] = h0; kh[2*ARRU + i*2+1] = h1;
            kh[3*ARRU + i*2] = l0; kh[3*ARRU + i*2+1] = l1;
        }
    }
    __syncthreads();

    float o[8][4];
    #pragma unroll
    for (int nt = 0; nt < 8; nt++)
        #pragma unroll
        for (int j = 0; j < 4; j++) o[nt][j] = 0.0f;
    float mrow0 = -1e30f, mrow1 = -1e30f, lrow0 = 0.0f, lrow1 = 0.0f;

    constexpr int NT = T_SEQ / 64;
    for (int kt = 0; kt < NT; kt++) {
        const uint32_t so = (uint32_t)(kt & 1) * STAGE_BYTES;
        const bool more = (kt + 1 < NT);

        if (more) {   // LDG tile kt+1 — latency covered by the MMA block below
            const size_t roff = (size_t)((kt + 1) * 64 + pr) * (3*C_DIM);
            #pragma unroll
            for (int i = 0; i < 4; i++) {
                pk[i] = *(const float4*)(kbase + roff + i * 4);
                pv[i] = *(const float4*)(vbase + roff + i * 4);
            }
        }

        // ---- S = Q K^T (bf16x3) ----
        float s[8][4];
        #pragma unroll
        for (int nt = 0; nt < 8; nt++)
            #pragma unroll
            for (int j = 0; j < 4; j++) s[nt][j] = 0.0f;

        #pragma unroll
        for (int ks = 0; ks < 4; ks++) {
            #pragma unroll
            for (int kb = 0; kb < 4; kb++) {
                const uint32_t off = so +
                    ((uint32_t)(kb * 16 + (t >> 1) * 8 + rl) * NKROW + ks * 8 + (t & 1) * 4) * 4;
                uint32_t rh[4], rlo[4];
                LDSM4(rh, sb + off);
                LDSM4(rlo, sb + ARRU * 4 + off);
                MMA_BF16(s[2*kb],   qh[ks], rh);
                MMA_BF16(s[2*kb],   ql[ks], rh);
                MMA_BF16(s[2*kb],   qh[ks], rlo);
                MMA_BF16(s[2*kb+1], qh[ks], rh + 2);
                MMA_BF16(s[2*kb+1], ql[ks], rh + 2);
                MMA_BF16(s[2*kb+1], qh[ks], rlo + 2);
            }
        }

        // ---- online softmax in fragment layout ----
        float rm0 = -1e30f, rm1 = -1e30f;
        #pragma unroll
        for (int nt = 0; nt < 8; nt++) {
            rm0 = fmaxf(rm0, fmaxf(s[nt][0], s[nt][1]));
            rm1 = fmaxf(rm1, fmaxf(s[nt][2], s[nt][3]));
        }
        rm0 = fmaxf(rm0, __shfl_xor_sync(0xffffffffu, rm0, 1));
        rm0 = fmaxf(rm0, __shfl_xor_sync(0xffffffffu, rm0, 2));
        rm1 = fmaxf(rm1, __shfl_xor_sync(0xffffffffu, rm1, 1));
        rm1 = fmaxf(rm1, __shfl_xor_sync(0xffffffffu, rm1, 2));
        const float mn0 = fmaxf(mrow0, rm0);
        const float mn1 = fmaxf(mrow1, rm1);
        const float sc0 = exp2_fast(mrow0 - mn0);
        const float sc1 = exp2_fast(mrow1 - mn1);
        mrow0 = mn0; mrow1 = mn1;

        float rs0 = 0.0f, rs1 = 0.0f;
        #pragma unroll
        for (int nt = 0; nt < 8; nt++) {
            s[nt][0] = exp2_fast(s[nt][0] - mn0);
            s[nt][1] = exp2_fast(s[nt][1] - mn0);
            s[nt][2] = exp2_fast(s[nt][2] - mn1);
            s[nt][3] = exp2_fast(s[nt][3] - mn1);
            rs0 += s[nt][0] + s[nt][1];
            rs1 += s[nt][2] + s[nt][3];
        }
        rs0 += __shfl_xor_sync(0xffffffffu, rs0, 1);
        rs0 += __shfl_xor_sync(0xffffffffu, rs0, 2);
        rs1 += __shfl_xor_sync(0xffffffffu, rs1, 1);
        rs1 += __shfl_xor_sync(0xffffffffu, rs1, 2);
        lrow0 = lrow0 * sc0 + rs0;
        lrow1 = lrow1 * sc1 + rs1;

        #pragma unroll
        for (int nt = 0; nt < 8; nt++) {
            o[nt][0] *= sc0; o[nt][1] *= sc0;
            o[nt][2] *= sc1; o[nt][3] *= sc1;
        }

        // ---- O += P V (bf16x3) ----
        #pragma unroll
        for (int ks2 = 0; ks2 < 4; ks2++) {
            uint32_t pah[4], pal[4];
            split2(s[2*ks2][0],   s[2*ks2][1],   pah[0], pal[0]);
            split2(s[2*ks2][2],   s[2*ks2][3],   pah[1], pal[1]);
            split2(s[2*ks2+1][0], s[2*ks2+1][1], pah[2], pal[2]);
            split2(s[2*ks2+1][2], s[2*ks2+1][3], pah[3], pal[3]);
            #pragma unroll
            for (int db = 0; db < 4; db++) {
                const uint32_t off = so +
                    ((uint32_t)(ks2 * 16 + (t & 1) * 8 + rl) * NKROW + db * 8 + (t >> 1) * 4) * 4;
                uint32_t rvh[4], rvl[4];
                LDSM4T(rvh, sb + 2 * ARRU * 4 + off);
                LDSM4T(rvl, sb + 3 * ARRU * 4 + off);
                MMA_BF16(o[2*db],   pah, rvh);
                MMA_BF16(o[2*db],   pal, rvh);
                MMA_BF16(o[2*db],   pah, rvl);
                MMA_BF16(o[2*db+1], pah, rvh + 2);
                MMA_BF16(o[2*db+1], pal, rvh + 2);
                MMA_BF16(o[2*db+1], pah, rvl + 2);
            }
        }

        if (more) {   // split + STS tile kt+1 into the other stage
            uint32_t* kh = dsm + ((kt + 1) & 1) * STAGE_U32 + pIdx;
            #pragma unroll
            for (int i = 0; i < 4; i++) {
                uint32_t h0, l0, h1, l1;
                split2(pk[i].x, pk[i].y, h0, l0); split2(pk[i].z, pk[i].w, h1, l1);
                kh[i*2] = h0; kh[i*2+1] = h1;
                kh[ARRU + i*2] = l0; kh[ARRU + i*2+1] = l1;
                split2(pv[i].x, pv[i].y, h0, l0); split2(pv[i].z, pv[i].w, h1, l1);
                kh[2*ARRU + i*2] = h0; kh[2*ARRU + i*2+1] = h1;
                kh[3*ARRU + i*2] = l0; kh[3*ARRU + i*2+1] = l1;
            }
        }
        __syncthreads();
    }

    // ---- epilogue: O / l -> g_att [b, t, h*64 + d] ----
    const float inv0 = 1.0f / lrow0;
    const float inv1 = 1.0f / lrow1;
    const int qrow = m0 + w * 16 + g;
    float* orow0 = attout + (size_t)(b * T_SEQ + qrow) * C_DIM + h * H_DIM;
    float* orow1 = orow0 + (size_t)8 * C_DIM;
    #pragma unroll
    for (int nt = 0; nt < 8; nt++) {
        float2 v0, v1;
        v0.x = o[nt][0] * inv0; v0.y = o[nt][1] * inv0;
        v1.x = o[nt][2] * inv1; v1.y = o[nt][3] * inv1;
        *(float2*)(orow0 + nt * 8 + tig * 2) = v0;
        *(float2*)(orow1 + nt * 8 + tig * 2) = v1;
    }
}

// ===========================================================================
extern "C" void kernel_launch(void* const* d_in, const int* in_sizes, int n_in,
                              void* d_out, int out_size)
{
    (void)in_sizes; (void)n_in; (void)out_size;
    const float* x      = (const float*)d_in[0];
    const float* qkv_w  = (const float*)d_in[1];
    const float* qkv_b  = (const float*)d_in[2];
    const float* proj_w = (const float*)d_in[3];
    const float* proj_b = (const float*)d_in[4];
    float* out = (float*)d_out;

    float *qkv_ptr, *att_ptr;
    cudaGetSymbolAddress((void**)&qkv_ptr, g_qkv);
    cudaGetSymbolAddress((void**)&att_ptr, g_att);

    cudaFuncSetAttribute(attn_mma, cudaFuncAttributeMaxDynamicSharedMemorySize, ATTN_DSMEM);

    // 1) QKV GEMM: [8192,768] x [2304,768]^T + b -> g_qkv   (bf16x3 tensor)
    gemm_bf16x3<<<dim3(3*C_DIM/128, M_ROWS/128), 256>>>(x, qkv_w, qkv_b, qkv_ptr, 3*C_DIM, C_DIM);
    // 2) MMA flash attention (double-buffered K/V) -> g_att
    attn_mma<<<dim3(T_SEQ/128, N_HEADS, N_BATCH), 256, ATTN_DSMEM>>>(qkv_ptr, att_ptr);
    // 3) proj GEMM: [8192,768] x [768,768]^T + b -> out     (bf16x3 tensor)
    gemm_bf16x3<<<dim3(C_DIM/128, M_ROWS/128), 256>>>(att_ptr, proj_w, proj_b, out, C_DIM, C_DIM);
}

// round 8
// speedup vs baseline: 1.7983x; 1.0492x over previous
#include <cuda_runtime.h>
#include <cuda_bf16.h>
#include <cstdint>

// Problem constants
#define T_SEQ   2048
#define N_BATCH 4
#define C_DIM   768
#define N_HEADS 12
#define H_DIM   64
#define M_ROWS  (N_BATCH * T_SEQ)   // 8192

// ---------------------------------------------------------------------------
// Global scratch (static __device__ arrays; allocation-free per harness rules)
// ---------------------------------------------------------------------------
__device__ float g_qkv[(size_t)M_ROWS * 3 * C_DIM];                       // f32 QKV
__device__ __align__(16) __nv_bfloat16 g_xhi[(size_t)M_ROWS * C_DIM];
__device__ __align__(16) __nv_bfloat16 g_xlo[(size_t)M_ROWS * C_DIM];
__device__ __align__(16) __nv_bfloat16 g_wqh[(size_t)3 * C_DIM * C_DIM];
__device__ __align__(16) __nv_bfloat16 g_wql[(size_t)3 * C_DIM * C_DIM];
__device__ __align__(16) __nv_bfloat16 g_wph[(size_t)C_DIM * C_DIM];
__device__ __align__(16) __nv_bfloat16 g_wpl[(size_t)C_DIM * C_DIM];
#define KVPLANE ((size_t)N_BATCH * N_HEADS * T_SEQ * H_DIM)
__device__ __align__(16) __nv_bfloat16 g_khi[KVPLANE];
__device__ __align__(16) __nv_bfloat16 g_klo[KVPLANE];
__device__ __align__(16) __nv_bfloat16 g_vhi[KVPLANE];
__device__ __align__(16) __nv_bfloat16 g_vlo[KVPLANE];
__device__ __align__(16) __nv_bfloat16 g_ahi[(size_t)M_ROWS * C_DIM];
__device__ __align__(16) __nv_bfloat16 g_alo[(size_t)M_ROWS * C_DIM];

// ===========================================================================
// helpers
// ===========================================================================
__device__ __forceinline__ uint32_t smem_u32(const void* p) {
    uint32_t a;
    asm("{ .reg .u64 t; cvta.to.shared.u64 t, %1; cvt.u32.u64 %0, t; }"
        : "=r"(a) : "l"(p));
    return a;
}

#define LDSM4(r, addr) \
    asm volatile("ldmatrix.sync.aligned.m8n8.x4.shared.b16 {%0,%1,%2,%3}, [%4];" \
                 : "=r"((r)[0]), "=r"((r)[1]), "=r"((r)[2]), "=r"((r)[3]) \
                 : "r"(addr))

#define LDSM4T(r, addr) \
    asm volatile("ldmatrix.sync.aligned.m8n8.x4.trans.shared.b16 {%0,%1,%2,%3}, [%4];" \
                 : "=r"((r)[0]), "=r"((r)[1]), "=r"((r)[2]), "=r"((r)[3]) \
                 : "r"(addr))

#define MMA_BF16(c, a, b) \
    asm volatile("mma.sync.aligned.m16n8k16.row.col.f32.bf16.bf16.f32 " \
                 "{%0,%1,%2,%3}, {%4,%5,%6,%7}, {%8,%9}, {%0,%1,%2,%3};" \
                 : "+f"((c)[0]), "+f"((c)[1]), "+f"((c)[2]), "+f"((c)[3]) \
                 : "r"((a)[0]), "r"((a)[1]), "r"((a)[2]), "r"((a)[3]), \
                   "r"((b)[0]), "r"((b)[1]))

#define CP16(sdst, gsrc) \
    asm volatile("cp.async.ca.shared.global [%0], [%1], 16;" \
                 :: "r"(sdst), "l"(gsrc) : "memory")
#define CP_COMMIT() asm volatile("cp.async.commit_group;" ::: "memory")
#define CP_WAIT0()  asm volatile("cp.async.wait_group 0;" ::: "memory")
#define CP_WAIT1()  asm volatile("cp.async.wait_group 1;" ::: "memory")

__device__ __forceinline__ void split2(float x, float y, uint32_t& hi, uint32_t& lo) {
    __nv_bfloat16 hx = __float2bfloat16_rn(x);
    __nv_bfloat16 hy = __float2bfloat16_rn(y);
    float lx = x - __bfloat162float(hx);
    float ly = y - __bfloat162float(hy);
    __nv_bfloat16 lxh = __float2bfloat16_rn(lx);
    __nv_bfloat16 lyh = __float2bfloat16_rn(ly);
    hi = (uint32_t)__bfloat16_as_ushort(hx) | ((uint32_t)__bfloat16_as_ushort(hy) << 16);
    lo = (uint32_t)__bfloat16_as_ushort(lxh) | ((uint32_t)__bfloat16_as_ushort(lyh) << 16);
}

// Fast 2^t on the FMA pipe (t <= 0 in softmax use). rel err ~3e-6.
__device__ __forceinline__ float exp2_fast(float t) {
    t = fmaxf(t, -100.0f);
    float n = rintf(t);
    float f = t - n;
    float u = f * 0.6931471805599453f;
    float r = 8.3333333e-3f;
    r = fmaf(r, u, 4.1666667e-2f);
    r = fmaf(r, u, 1.6666667e-1f);
    r = fmaf(r, u, 5.0e-1f);
    r = fmaf(r, u, 1.0f);
    r = fmaf(r, u, 1.0f);
    int e = (int)n;
    return r * __int_as_float((e + 127) << 23);
}

// ===========================================================================
// Prep kernels: split f32 -> bf16 hi/lo planes (memory-bound, run once/call)
// ===========================================================================
__global__ void split_plane_kernel(const float4* __restrict__ in,
                                   uint2* __restrict__ hi, uint2* __restrict__ lo,
                                   int n4)
{
    int i = blockIdx.x * blockDim.x + threadIdx.x;
    if (i >= n4) return;
    float4 v = in[i];
    uint32_t h0, l0, h1, l1;
    split2(v.x, v.y, h0, l0);
    split2(v.z, v.w, h1, l1);
    hi[i] = make_uint2(h0, h1);
    lo[i] = make_uint2(l0, l1);
}

// split K,V sections of g_qkv into per-(b,h) planes [B,H,T,64]
__global__ void split_kv_kernel(const float* __restrict__ qkv)
{
    int i4 = blockIdx.x * blockDim.x + threadIdx.x;
    const int total = N_BATCH * T_SEQ * C_DIM / 4;
    if (i4 >= total) return;
    int flat = i4 * 4;
    int b = flat / (T_SEQ * C_DIM);
    int rem = flat - b * (T_SEQ * C_DIM);
    int t = rem / C_DIM;
    int c = rem - t * C_DIM;
    int h = c >> 6, d = c & 63;
    size_t src = (size_t)(b * T_SEQ + t) * (3 * C_DIM);
    size_t dst = ((size_t)(b * N_HEADS + h) * T_SEQ + t) * H_DIM + d;
    float4 kv = *(const float4*)(qkv + src + C_DIM + c);
    float4 vv = *(const float4*)(qkv + src + 2 * C_DIM + c);
    uint32_t h0, l0, h1, l1;
    split2(kv.x, kv.y, h0, l0); split2(kv.z, kv.w, h1, l1);
    *(uint2*)(g_khi + dst) = make_uint2(h0, h1);
    *(uint2*)(g_klo + dst) = make_uint2(l0, l1);
    split2(vv.x, vv.y, h0, l0); split2(vv.z, vv.w, h1, l1);
    *(uint2*)(g_vhi + dst) = make_uint2(h0, h1);
    *(uint2*)(g_vlo + dst) = make_uint2(l0, l1);
}

// ===========================================================================
// bf16x3 tensor-core GEMM on PRE-SPLIT planes, cp.async 3-stage pipeline.
// C[M,N] = A[M,K] @ W[N,K]^T + bias[N]. Block 128x128, BK=32, 8 warps.
// ===========================================================================
#define SROW 40                         // halves per smem row (32 data + 8 pad)
#define G_ARRB (128 * SROW * 2)         // bytes per array (10240)
#define G_STGB (4 * G_ARRB)             // Ahi,Alo,Bhi,Blo per stage (40960)
#define GEMM_DSMEM (3 * G_STGB)         // 122880

__global__ __launch_bounds__(256, 1)
void gemm_planes(const __nv_bfloat16* __restrict__ Ahi,
                 const __nv_bfloat16* __restrict__ Alo,
                 const __nv_bfloat16* __restrict__ Bhi,
                 const __nv_bfloat16* __restrict__ Blo,
                 const float* __restrict__ bias,
                 float* __restrict__ C,
                 int Nd, int Kd)
{
    extern __shared__ __align__(16) char dsmg[];
    const uint32_t sb = smem_u32(dsmg);

    const int tid  = threadIdx.x;
    const int lane = tid & 31;
    const int wid  = tid >> 5;
    const int wm   = wid & 1;
    const int wn   = wid >> 1;
    const int bn = blockIdx.x, bm = blockIdx.y;

    // ---- producer: plane p = tid>>6, rows r2,r2+1, 4 chunks each ----
    const int p  = tid >> 6;
    const int r2 = (tid & 63) * 2;
    const __nv_bfloat16* pl = (p == 0) ? Ahi : (p == 1) ? Alo : (p == 2) ? Bhi : Blo;
    const int baseRow = ((p < 2) ? bm : bn) * 128;
    const char* g0 = (const char*)(pl + (size_t)(baseRow + r2) * Kd);
    const char* g1 = (const char*)(pl + (size_t)(baseRow + r2 + 1) * Kd);
    const uint32_t s0 = sb + (uint32_t)p * G_ARRB + (uint32_t)r2 * 80;
    const uint32_t s1 = s0 + 80;

    float acc[4][4][4];
    #pragma unroll
    for (int mt = 0; mt < 4; mt++)
        #pragma unroll
        for (int nt = 0; nt < 4; nt++)
            #pragma unroll
            for (int q = 0; q < 4; q++) acc[mt][nt][q] = 0.0f;

    const uint32_t aOff = ((uint32_t)(wm * 64 + (lane & 15)) * SROW + (lane >> 4) * 8) * 2;
    const uint32_t bOff = ((uint32_t)(wn * 32 + ((lane >> 4) & 1) * 8 + (lane & 7)) * SROW
                          + ((lane >> 3) & 1) * 8) * 2;
    const uint32_t aHiB = sb + aOff;
    const uint32_t aLoB = sb + G_ARRB + aOff;
    const uint32_t bHiB = sb + 2 * G_ARRB + bOff;
    const uint32_t bLoB = sb + 3 * G_ARRB + bOff;

    const int nch = Kd / 32;

    // prologue: chunk 0 -> stage 0
    {
        #pragma unroll
        for (int c = 0; c < 4; c++) {
            CP16(s0 + c * 16, g0 + c * 16);
            CP16(s1 + c * 16, g1 + c * 16);
        }
        CP_COMMIT();
    }

    for (int ch = 0; ch < nch; ch++) {
        if (ch + 1 < nch) {
            const uint32_t sw = (uint32_t)((ch + 1) % 3) * G_STGB;
            const int gb = (ch + 1) * 64;
            #pragma unroll
            for (int c = 0; c < 4; c++) {
                CP16(s0 + sw + c * 16, g0 + gb + c * 16);
                CP16(s1 + sw + c * 16, g1 + gb + c * 16);
            }
            CP_COMMIT();
            CP_WAIT1();
        } else {
            CP_WAIT0();
        }
        __syncthreads();

        const uint32_t so = (uint32_t)(ch % 3) * G_STGB;
        #pragma unroll
        for (int ks = 0; ks < 2; ks++) {
            uint32_t ah[4][4], al[4][4], bh[4][2], bl[4][2];
            #pragma unroll
            for (int mt = 0; mt < 4; mt++) {
                const uint32_t ad = (uint32_t)(mt * 16 * SROW + ks * 16) * 2 + so;
                LDSM4(ah[mt], aHiB + ad);
                LDSM4(al[mt], aLoB + ad);
            }
            #pragma unroll
            for (int pp = 0; pp < 2; pp++) {
                const uint32_t bd = (uint32_t)(pp * 16 * SROW + ks * 16) * 2 + so;
                uint32_t r[4];
                LDSM4(r, bHiB + bd);
                bh[2*pp][0] = r[0]; bh[2*pp][1] = r[1];
                bh[2*pp+1][0] = r[2]; bh[2*pp+1][1] = r[3];
                LDSM4(r, bLoB + bd);
                bl[2*pp][0] = r[0]; bl[2*pp][1] = r[1];
                bl[2*pp+1][0] = r[2]; bl[2*pp+1][1] = r[3];
            }
            #pragma unroll
            for (int mt = 0; mt < 4; mt++)
                #pragma unroll
                for (int nt = 0; nt < 4; nt++) {
                    MMA_BF16(acc[mt][nt], ah[mt], bh[nt]);
                    MMA_BF16(acc[mt][nt], al[mt], bh[nt]);
                    MMA_BF16(acc[mt][nt], ah[mt], bl[nt]);
                }
        }
    }

    const int gid = lane >> 2, tig = lane & 3;
    const int row0 = bm * 128 + wm * 64;
    const int col0 = bn * 128 + wn * 32;
    #pragma unroll
    for (int mt = 0; mt < 4; mt++)
        #pragma unroll
        for (int nt = 0; nt < 4; nt++) {
            const int r  = row0 + mt * 16 + gid;
            const int cc = col0 + nt * 8 + tig * 2;
            const float2 bz = *(const float2*)(bias + cc);
            float2 o0, o1;
            o0.x = acc[mt][nt][0] + bz.x; o0.y = acc[mt][nt][1] + bz.y;
            o1.x = acc[mt][nt][2] + bz.x; o1.y = acc[mt][nt][3] + bz.y;
            *(float2*)(C + (size_t)r * Nd + cc)       = o0;
            *(float2*)(C + (size_t)(r + 8) * Nd + cc) = o1;
        }
}

// ===========================================================================
// MMA flash attention on PRE-SPLIT K/V planes, cp.async 3-stage pipeline.
// Block = 128 q-rows x 1 head, 8 warps x 16 q-rows. Compute core identical
// to the verified round-7 kernel. Epilogue writes O as bf16 hi/lo planes.
// ===========================================================================
#define NKROW 36                          // u32 per smem row (64 halves + pad)
#define ARRU  (64 * NKROW)                // u32 per 64x64 array (2304)
#define STAGE_U32 (4 * ARRU)              // Khi,Klo,Vhi,Vlo (9216)
#define STAGE_BYTES (STAGE_U32 * 4)       // 36864
#define ATTN_DSMEM (3 * STAGE_BYTES)      // 110592
#define QSCALE 11.541560327111707f        // 8 * log2(e)

__global__ __launch_bounds__(256, 1)
void attn_mma(const float* __restrict__ qkv)
{
    extern __shared__ __align__(16) uint32_t dsm[];

    const int tid  = threadIdx.x;
    const int lane = tid & 31;
    const int w    = tid >> 5;
    const int g    = lane >> 2;
    const int tig  = lane & 3;
    const int m0   = blockIdx.x * 128;
    const int h    = blockIdx.y;
    const int b    = blockIdx.z;

    const float* base = qkv + (size_t)b * T_SEQ * (3*C_DIM) + h * H_DIM;
    const uint32_t sb = smem_u32(dsm);

    // ---- producer: plane pp = tid>>6 (Khi,Klo,Vhi,Vlo), row rr = tid&63 ----
    const int pp = tid >> 6;
    const int rr = tid & 63;
    const __nv_bfloat16* kvpl = (pp == 0) ? g_khi : (pp == 1) ? g_klo
                               : (pp == 2) ? g_vhi : g_vlo;
    const char* gsrc0 = (const char*)(kvpl + ((size_t)(b * N_HEADS + h) * T_SEQ + rr) * H_DIM);
    const uint32_t sdst0 = sb + (uint32_t)pp * ARRU * 4 + (uint32_t)rr * 144;

    // prologue: tile 0 -> stage 0 (cp.async), Q -> stages 1&2 (STS), fragments
    {
        #pragma unroll
        for (int c = 0; c < 8; c++) CP16(sdst0 + c * 16, gsrc0 + c * 16);
        CP_COMMIT();
    }
    {
        const int r = tid >> 1;
        const int dblk = (tid & 1) * 32;
        const float* qrow = base + (size_t)(m0 + r) * (3*C_DIM) + dblk;
        uint32_t* dhi = dsm + STAGE_U32 + r * NKROW + dblk / 2;       // stage 1
        uint32_t* dlo = dsm + 2 * STAGE_U32 + r * NKROW + dblk / 2;   // stage 2
        #pragma unroll
        for (int i = 0; i < 8; i++) {
            float4 v = *(const float4*)(qrow + i * 4);
            uint32_t h0, l0, h1, l1;
            split2(v.x * QSCALE, v.y * QSCALE, h0, l0);
            split2(v.z * QSCALE, v.w * QSCALE, h1, l1);
            dhi[i*2] = h0; dhi[i*2+1] = h1;
            dlo[i*2] = l0; dlo[i*2+1] = l1;
        }
    }
    __syncthreads();

    uint32_t qh[4][4], ql[4][4];
    const int t = lane >> 3, rl = lane & 7;
    {
        #pragma unroll
        for (int ks = 0; ks < 4; ks++) {
            const uint32_t off =
                ((uint32_t)(w * 16 + (t & 1) * 8 + rl) * NKROW + ks * 8 + (t >> 1) * 4) * 4;
            LDSM4(qh[ks], sb + STAGE_BYTES + off);
            LDSM4(ql[ks], sb + 2 * STAGE_BYTES + off);
        }
    }
    __syncthreads();   // Q in registers; stages 1,2 free for the pipeline

    float o[8][4];
    #pragma unroll
    for (int nt = 0; nt < 8; nt++)
        #pragma unroll
        for (int j = 0; j < 4; j++) o[nt][j] = 0.0f;
    float mrow0 = -1e30f, mrow1 = -1e30f, lrow0 = 0.0f, lrow1 = 0.0f;

    constexpr int NT = T_SEQ / 64;
    for (int kt = 0; kt < NT; kt++) {
        if (kt + 1 < NT) {   // issue tile kt+1 -> stage (kt+1)%3
            const uint32_t sw = (uint32_t)((kt + 1) % 3) * STAGE_BYTES;
            const char* gs = gsrc0 + (size_t)(kt + 1) * 64 * H_DIM * 2;
            #pragma unroll
            for (int c = 0; c < 8; c++) CP16(sdst0 + sw + c * 16, gs + c * 16);
            CP_COMMIT();
            CP_WAIT1();
        } else {
            CP_WAIT0();
        }
        __syncthreads();

        const uint32_t so = (uint32_t)(kt % 3) * STAGE_BYTES;

        // ---- S = Q K^T (bf16x3) ----
        float s[8][4];
        #pragma unroll
        for (int nt = 0; nt < 8; nt++)
            #pragma unroll
            for (int j = 0; j < 4; j++) s[nt][j] = 0.0f;

        #pragma unroll
        for (int ks = 0; ks < 4; ks++) {
            #pragma unroll
            for (int kb = 0; kb < 4; kb++) {
                const uint32_t off = so +
                    ((uint32_t)(kb * 16 + (t >> 1) * 8 + rl) * NKROW + ks * 8 + (t & 1) * 4) * 4;
                uint32_t rh[4], rlo[4];
                LDSM4(rh, sb + off);
                LDSM4(rlo, sb + ARRU * 4 + off);
                MMA_BF16(s[2*kb],   qh[ks], rh);
                MMA_BF16(s[2*kb],   ql[ks], rh);
                MMA_BF16(s[2*kb],   qh[ks], rlo);
                MMA_BF16(s[2*kb+1], qh[ks], rh + 2);
                MMA_BF16(s[2*kb+1], ql[ks], rh + 2);
                MMA_BF16(s[2*kb+1], qh[ks], rlo + 2);
            }
        }

        // ---- online softmax in fragment layout ----
        float rm0 = -1e30f, rm1 = -1e30f;
        #pragma unroll
        for (int nt = 0; nt < 8; nt++) {
            rm0 = fmaxf(rm0, fmaxf(s[nt][0], s[nt][1]));
            rm1 = fmaxf(rm1, fmaxf(s[nt][2], s[nt][3]));
        }
        rm0 = fmaxf(rm0, __shfl_xor_sync(0xffffffffu, rm0, 1));
        rm0 = fmaxf(rm0, __shfl_xor_sync(0xffffffffu, rm0, 2));
        rm1 = fmaxf(rm1, __shfl_xor_sync(0xffffffffu, rm1, 1));
        rm1 = fmaxf(rm1, __shfl_xor_sync(0xffffffffu, rm1, 2));
        const float mn0 = fmaxf(mrow0, rm0);
        const float mn1 = fmaxf(mrow1, rm1);
        const float sc0 = exp2_fast(mrow0 - mn0);
        const float sc1 = exp2_fast(mrow1 - mn1);
        mrow0 = mn0; mrow1 = mn1;

        float rs0 = 0.0f, rs1 = 0.0f;
        #pragma unroll
        for (int nt = 0; nt < 8; nt++) {
            s[nt][0] = exp2_fast(s[nt][0] - mn0);
            s[nt][1] = exp2_fast(s[nt][1] - mn0);
            s[nt][2] = exp2_fast(s[nt][2] - mn1);
            s[nt][3] = exp2_fast(s[nt][3] - mn1);
            rs0 += s[nt][0] + s[nt][1];
            rs1 += s[nt][2] + s[nt][3];
        }
        rs0 += __shfl_xor_sync(0xffffffffu, rs0, 1);
        rs0 += __shfl_xor_sync(0xffffffffu, rs0, 2);
        rs1 += __shfl_xor_sync(0xffffffffu, rs1, 1);
        rs1 += __shfl_xor_sync(0xffffffffu, rs1, 2);
        lrow0 = lrow0 * sc0 + rs0;
        lrow1 = lrow1 * sc1 + rs1;

        #pragma unroll
        for (int nt = 0; nt < 8; nt++) {
            o[nt][0] *= sc0; o[nt][1] *= sc0;
            o[nt][2] *= sc1; o[nt][3] *= sc1;
        }

        // ---- O += P V (bf16x3) ----
        #pragma unroll
        for (int ks2 = 0; ks2 < 4; ks2++) {
            uint32_t pah[4], pal[4];
            split2(s[2*ks2][0],   s[2*ks2][1],   pah[0], pal[0]);
            split2(s[2*ks2][2],   s[2*ks2][3],   pah[1], pal[1]);
            split2(s[2*ks2+1][0], s[2*ks2+1][1], pah[2], pal[2]);
            split2(s[2*ks2+1][2], s[2*ks2+1][3], pah[3], pal[3]);
            #pragma unroll
            for (int db = 0; db < 4; db++) {
                const uint32_t off = so +
                    ((uint32_t)(ks2 * 16 + (t & 1) * 8 + rl) * NKROW + db * 8 + (t >> 1) * 4) * 4;
                uint32_t rvh[4], rvl[4];
                LDSM4T(rvh, sb + 2 * ARRU * 4 + off);
                LDSM4T(rvl, sb + 3 * ARRU * 4 + off);
                MMA_BF16(o[2*db],   pah, rvh);
                MMA_BF16(o[2*db],   pal, rvh);
                MMA_BF16(o[2*db],   pah, rvl);
                MMA_BF16(o[2*db+1], pah, rvh + 2);
                MMA_BF16(o[2*db+1], pal, rvh + 2);
                MMA_BF16(o[2*db+1], pah, rvl + 2);
            }
        }
    }

    // ---- epilogue: O / l -> bf16 hi/lo planes for the proj GEMM ----
    const float inv0 = 1.0f / lrow0;
    const float inv1 = 1.0f / lrow1;
    const int qrow = m0 + w * 16 + g;
    const size_t off0 = (size_t)(b * T_SEQ + qrow) * C_DIM + h * H_DIM;
    const size_t off1 = off0 + (size_t)8 * C_DIM;
    #pragma unroll
    for (int nt = 0; nt < 8; nt++) {
        uint32_t hh, ll;
        split2(o[nt][0] * inv0, o[nt][1] * inv0, hh, ll);
        *(uint32_t*)(g_ahi + off0 + nt * 8 + tig * 2) = hh;
        *(uint32_t*)(g_alo + off0 + nt * 8 + tig * 2) = ll;
        split2(o[nt][2] * inv1, o[nt][3] * inv1, hh, ll);
        *(uint32_t*)(g_ahi + off1 + nt * 8 + tig * 2) = hh;
        *(uint32_t*)(g_alo + off1 + nt * 8 + tig * 2) = ll;
    }
}

// ===========================================================================
extern "C" void kernel_launch(void* const* d_in, const int* in_sizes, int n_in,
                              void* d_out, int out_size)
{
    (void)in_sizes; (void)n_in; (void)out_size;
    const float* x      = (const float*)d_in[0];
    const float* qkv_w  = (const float*)d_in[1];
    const float* qkv_b  = (const float*)d_in[2];
    const float* proj_w = (const float*)d_in[3];
    const float* proj_b = (const float*)d_in[4];
    float* out = (float*)d_out;

    float* qkv_ptr;
    cudaGetSymbolAddress((void**)&qkv_ptr, g_qkv);
    __nv_bfloat16 *xhi, *xlo, *wqh, *wql, *wph, *wpl, *ahi, *alo;
    cudaGetSymbolAddress((void**)&xhi, g_xhi);
    cudaGetSymbolAddress((void**)&xlo, g_xlo);
    cudaGetSymbolAddress((void**)&wqh, g_wqh);
    cudaGetSymbolAddress((void**)&wql, g_wql);
    cudaGetSymbolAddress((void**)&wph, g_wph);
    cudaGetSymbolAddress((void**)&wpl, g_wpl);
    cudaGetSymbolAddress((void**)&ahi, g_ahi);
    cudaGetSymbolAddress((void**)&alo, g_alo);

    cudaFuncSetAttribute(gemm_planes, cudaFuncAttributeMaxDynamicSharedMemorySize, GEMM_DSMEM);
    cudaFuncSetAttribute(attn_mma, cudaFuncAttributeMaxDynamicSharedMemorySize, ATTN_DSMEM);

    // 0) pre-split inputs into bf16 hi/lo planes
    {
        const int n4x = M_ROWS * C_DIM / 4;
        split_plane_kernel<<<(n4x + 255) / 256, 256>>>(
            (const float4*)x, (uint2*)xhi, (uint2*)xlo, n4x);
        const int n4q = 3 * C_DIM * C_DIM / 4;
        split_plane_kernel<<<(n4q + 255) / 256, 256>>>(
            (const float4*)qkv_w, (uint2*)wqh, (uint2*)wql, n4q);
        const int n4p = C_DIM * C_DIM / 4;
        split_plane_kernel<<<(n4p + 255) / 256, 256>>>(
            (const float4*)proj_w, (uint2*)wph, (uint2*)wpl, n4p);
    }

    // 1) QKV GEMM: planes -> g_qkv (f32)
    gemm_planes<<<dim3(3*C_DIM/128, M_ROWS/128), 256, GEMM_DSMEM>>>(
        xhi, xlo, wqh, wql, qkv_b, qkv_ptr, 3*C_DIM, C_DIM);

    // 2) split K/V once into per-(b,h) bf16 planes
    {
        const int n4 = N_BATCH * T_SEQ * C_DIM / 4;
        split_kv_kernel<<<(n4 + 255) / 256, 256>>>(qkv_ptr);
    }

    // 3) MMA flash attention -> g_ahi/g_alo planes
    attn_mma<<<dim3(T_SEQ/128, N_HEADS, N_BATCH), 256, ATTN_DSMEM>>>(qkv_ptr);

    // 4) proj GEMM: planes -> out (f32)
    gemm_planes<<<dim3(C_DIM/128, M_ROWS/128), 256, GEMM_DSMEM>>>(
        ahi, alo, wph, wpl, proj_b, out, C_DIM, C_DIM);
}